// round 4
// baseline (speedup 1.0000x reference)
#include <cuda_runtime.h>
#include <cstdint>

#define Bn 64
#define Sn 128
#define Dn 512
#define Tn 64
#define N3 1536      // 3*D
#define NR 2048      // D + 3*D (combined q|gh GEMM width)
#define GK 515       // D + 3
#define GKP 528      // padded to multiple of 16
#define NCTA 128

// ---------------- scratch (device globals; no allocation) ----------------
__device__ float g_Uk[Bn * Sn * Dn];              // [B,S,D] keys projection
__device__ float g_h[Bn * Dn];                    // hidden state
__device__ float g_recpart[4][Bn * NR];           // split-K partials of [q | gh]
__device__ float g_gipart[4][Bn * N3];            // split-K partials of gi
__device__ float g_gin[Bn * GKP];                 // [ctx | x | zero-pad]
__device__ float g_Wpad[N3 * GKP];                // W_ih zero-padded to K=528
__device__ float g_Wcat[NR * Dn];                 // [Wa_w^T ; W_hh], NT layout [N,K]
__device__ float g_scores[Bn * Sn];               // attention scores
__device__ unsigned g_arrive;                     // monotonic barrier counters
__device__ unsigned g_release;                    //   (replay-safe: never reset)
__device__ unsigned g_bsync[Bn];                  // per-batch pair sync (reset in init)

__device__ __forceinline__ float tanh_fast(float x) {
    float y; asm("tanh.approx.f32 %0, %1;" : "=f"(y) : "f"(x)); return y;
}

// Replay-safe grid barrier: epoch is derived from the monotonic arrive count,
// so counters persist across graph replays without reset. NCTA must equal 128.
__device__ __forceinline__ void grid_sync() {
    __syncthreads();
    if (threadIdx.x == 0) {
        __threadfence();
        unsigned old;
        asm volatile("atom.release.gpu.add.u32 %0, [%1], 1;"
                     : "=r"(old) : "l"(&g_arrive) : "memory");
        const unsigned k = old >> 7;                 // barrier instance
        if ((old & 127u) == 127u) {
            asm volatile("st.release.gpu.u32 [%0], %1;"
                         :: "l"(&g_release), "r"(k + 1) : "memory");
        } else {
            unsigned r;
            do {
                asm volatile("ld.acquire.gpu.u32 %0, [%1];"
                             : "=r"(r) : "l"(&g_release) : "memory");
            } while (r < k + 1);
        }
        __threadfence();
    }
    __syncthreads();
}

struct SmemGemm { float As[16][68]; float Bs[16][68]; };
struct SmemScore { float qs[Dn]; float vas[Dn]; };
struct SmemCtx { float ws[Sn]; float red[8]; float smax, sinv; };
union SmemAll { SmemGemm g; SmemScore sc; SmemCtx cx; };

// C[64 x 64] tile of  C = A(MxK) * B  (+bias), BK=16, 256 threads, 4x4 microtile.
// NT=false: B row-major [K,N];  NT=true: B row-major [N,K].
template <bool NT>
__device__ __forceinline__ void gemm64(const float* __restrict__ A, int lda,
                                       const float* __restrict__ B, int ldb,
                                       float* __restrict__ C, int ldc,
                                       const float* __restrict__ bias,
                                       int m0, int n0, int k0, int kiters,
                                       SmemGemm& s)
{
    const int tid = threadIdx.x;
    const int tx = tid & 15, ty = tid >> 4;
    const int am = tid >> 2, ak = (tid & 3) << 2;
    float acc[4][4] = {};

    for (int it = 0; it < kiters; ++it) {
        const int k = k0 + it * 16;
        float4 a4 = *(const float4*)&A[(size_t)(m0 + am) * lda + k + ak];
        float4 b4;
        if (NT) {
            b4 = *(const float4*)&B[(size_t)(n0 + am) * ldb + k + ak];
        } else {
            const int bk = tid >> 4, bn = (tid & 15) << 2;
            b4 = *(const float4*)&B[(size_t)(k + bk) * ldb + n0 + bn];
        }
        __syncthreads();
        s.As[ak + 0][am] = a4.x; s.As[ak + 1][am] = a4.y;
        s.As[ak + 2][am] = a4.z; s.As[ak + 3][am] = a4.w;
        if (NT) {
            s.Bs[ak + 0][am] = b4.x; s.Bs[ak + 1][am] = b4.y;
            s.Bs[ak + 2][am] = b4.z; s.Bs[ak + 3][am] = b4.w;
        } else {
            const int bk = tid >> 4, bn = (tid & 15) << 2;
            *(float4*)&s.Bs[bk][bn] = b4;
        }
        __syncthreads();
        #pragma unroll
        for (int kk = 0; kk < 16; ++kk) {
            float4 av = *(const float4*)&s.As[kk][ty << 2];
            float4 bv = *(const float4*)&s.Bs[kk][tx << 2];
            float a[4] = {av.x, av.y, av.z, av.w};
            float b[4] = {bv.x, bv.y, bv.z, bv.w};
            #pragma unroll
            for (int u = 0; u < 4; ++u)
                #pragma unroll
                for (int v = 0; v < 4; ++v)
                    acc[u][v] += a[u] * b[v];
        }
    }

    float4 bi = make_float4(0.f, 0.f, 0.f, 0.f);
    if (bias) bi = *(const float4*)&bias[n0 + (tx << 2)];
    #pragma unroll
    for (int u = 0; u < 4; ++u) {
        float4 o;
        o.x = acc[u][0] + bi.x; o.y = acc[u][1] + bi.y;
        o.z = acc[u][2] + bi.z; o.w = acc[u][3] + bi.w;
        *(float4*)&C[(size_t)(m0 + (ty << 2) + u) * ldc + n0 + (tx << 2)] = o;
    }
}

// ---------------- the persistent kernel ----------------
__global__ void __launch_bounds__(256, 1)
k_persist(const float* __restrict__ e_all,
          const float* __restrict__ e_last,
          const float* __restrict__ Wa_w,
          const float* __restrict__ Wa_b,
          const float* __restrict__ Ua_w,
          const float* __restrict__ Ua_b,
          const float* __restrict__ Va_w,
          const float* __restrict__ Va_b,
          const float* __restrict__ W_ih,
          const float* __restrict__ W_hh,
          const float* __restrict__ b_ih,
          const float* __restrict__ b_hh,
          const float* __restrict__ Wo_w,
          const float* __restrict__ Wo_b,
          float* __restrict__ d_outputs,
          float* __restrict__ hT,
          float* __restrict__ cross)
{
    __shared__ SmemAll sm;
    const int cta = blockIdx.x;
    const int tid = threadIdx.x;
    const int lane = tid & 31, wid = tid >> 5;
    const int gthr = cta * 256 + tid;

    // ---------- init ----------
    for (int j = gthr; j < Bn * Dn; j += NCTA * 256) g_h[j] = e_last[j];
    if (gthr < Bn * 16) {                 // zero x + pad region of gin
        int b0 = gthr >> 4, k = gthr & 15;
        g_gin[b0 * GKP + Dn + k] = 0.f;
    }
    if (cta == 0 && tid < Bn) g_bsync[tid] = 0;
    for (int j = gthr; j < N3 * GKP; j += NCTA * 256) {
        int n = j / GKP, k = j - n * GKP;
        g_Wpad[j] = (k < GK) ? W_ih[n * GK + k] : 0.f;
    }
    for (int j = gthr; j < NR * Dn; j += NCTA * 256) {
        int n = j >> 9, k = j & 511;
        g_Wcat[j] = (n < Dn) ? Wa_w[k * Dn + n] : W_hh[(size_t)(n - Dn) * Dn + k];
    }
    grid_sync();

    // ---------- Uk = e_all @ Ua_w + Ua_b  (1024 tiles, 8 per CTA) ----------
    for (int i = 0; i < 8; ++i) {
        const int t2 = cta + (i << 7);
        const int nx = t2 & 7, my = t2 >> 3;
        gemm64<false>(e_all, Dn, Ua_w, Dn, g_Uk, Dn, Ua_b,
                      my * 64, nx * 64, 0, 32, sm.g);
    }
    grid_sync();

    const int b = cta >> 1, half = cta & 1;

    // ---------- decode loop ----------
    for (int t = 0; t < Tn; ++t) {
        // Phase A: [q | gh] partials = h @ Wcat^T  (+ out_{t-1} on CTA 0)
        {
            const int part = cta & 3, nt = cta >> 2;
            gemm64<true>(g_h, Dn, g_Wcat, Dn, g_recpart[part], NR, nullptr,
                         0, nt * 64, part * 128, 8, sm.g);
            if (cta == 0 && t > 0 && tid < 192) {
                int bb = tid / 3, c = tid - bb * 3;
                const float* hr = &g_h[bb * Dn];
                float acc = Wo_b[c];
                #pragma unroll 4
                for (int k = 0; k < Dn; ++k) acc += hr[k] * Wo_w[k * 3 + c];
                d_outputs[((size_t)bb * Tn + (t - 1)) * 3 + c] = acc;
                g_gin[bb * GKP + Dn + c] = acc;
            }
        }
        grid_sync();

        // Phase B: scores — CTA handles 64 s-rows of batch b (8 per warp)
        {
            for (int d = tid; d < Dn; d += 256) {
                float q = Wa_b[d];
                #pragma unroll
                for (int p = 0; p < 4; ++p) q += g_recpart[p][b * NR + d];
                sm.sc.qs[d] = q;
                sm.sc.vas[d] = Va_w[d];
            }
            __syncthreads();
            const float vb0 = Va_b[0];
            #pragma unroll
            for (int r = 0; r < 8; ++r) {
                const int s = half * 64 + wid * 8 + r;
                const float4* uk4 = (const float4*)(g_Uk + ((size_t)b * Sn + s) * Dn);
                float sum = 0.f;
                #pragma unroll
                for (int i = 0; i < 4; ++i) {
                    const int v = lane + (i << 5);
                    float4 u = uk4[v];
                    float4 q4 = *(const float4*)&sm.sc.qs[v << 2];
                    float4 a4 = *(const float4*)&sm.sc.vas[v << 2];
                    sum += tanh_fast(q4.x + u.x) * a4.x;
                    sum += tanh_fast(q4.y + u.y) * a4.y;
                    sum += tanh_fast(q4.z + u.z) * a4.z;
                    sum += tanh_fast(q4.w + u.w) * a4.w;
                }
                #pragma unroll
                for (int o = 16; o > 0; o >>= 1)
                    sum += __shfl_down_sync(0xffffffffu, sum, o);
                if (lane == 0) g_scores[b * Sn + s] = sum + vb0;
            }
        }
        // pair sync: the 2 CTAs of batch b exchange scores
        __syncthreads();
        if (tid == 0) {
            __threadfence();
            asm volatile("red.release.gpu.add.u32 [%0], %1;"
                         :: "l"(&g_bsync[b]), "r"(1u) : "memory");
            const unsigned target = 2u * (unsigned)(t + 1);
            unsigned r;
            do {
                asm volatile("ld.acquire.gpu.u32 %0, [%1];"
                             : "=r"(r) : "l"(&g_bsync[b]) : "memory");
            } while (r < target);
            __threadfence();
        }
        __syncthreads();

        // Phase C: softmax (redundant in pair) + ctx slice (256 cols)
        {
            float sc = (tid < Sn) ? g_scores[b * Sn + tid] : -3.4e38f;
            float v = sc;
            #pragma unroll
            for (int o = 16; o > 0; o >>= 1)
                v = fmaxf(v, __shfl_xor_sync(0xffffffffu, v, o));
            if (lane == 0) sm.cx.red[wid] = v;
            __syncthreads();
            if (tid == 0) {
                float m = sm.cx.red[0];
                #pragma unroll
                for (int i = 1; i < 8; ++i) m = fmaxf(m, sm.cx.red[i]);
                sm.cx.smax = m;
            }
            __syncthreads();
            float e = (tid < Sn) ? __expf(sc - sm.cx.smax) : 0.f;
            float es = e;
            #pragma unroll
            for (int o = 16; o > 0; o >>= 1)
                es += __shfl_xor_sync(0xffffffffu, es, o);
            if (lane == 0) sm.cx.red[wid] = es;
            __syncthreads();
            if (tid == 0) {
                float s2 = 0.f;
                #pragma unroll
                for (int i = 0; i < 8; ++i) s2 += sm.cx.red[i];
                sm.cx.sinv = 1.f / s2;
            }
            __syncthreads();
            if (tid < Sn) {
                float w = e * sm.cx.sinv;
                sm.cx.ws[tid] = w;
                if (half == 0) cross[((size_t)b * Tn + t) * Sn + tid] = w;
            }
            __syncthreads();

            const int d = half * 256 + tid;
            const float* eb = e_all + (size_t)b * Sn * Dn + d;
            float a = 0.f;
            #pragma unroll 8
            for (int s = 0; s < Sn; ++s)
                a += sm.cx.ws[s] * eb[(size_t)s * Dn];
            g_gin[b * GKP + d] = a;
        }
        grid_sync();

        // Phase D: gi partials = gin @ Wpad^T  (96 work items)
        if (cta < 96) {
            const int part = cta & 3, nt = cta >> 2;
            const int k0 = (part < 3) ? part * 128 : 384;
            const int ki = (part < 3) ? 8 : 9;
            gemm64<true>(g_gin, GKP, g_Wpad, GKP, g_gipart[part], N3, nullptr,
                         0, nt * 64, k0, ki, sm.g);
        }
        grid_sync();

        // Phase E: GRU gates (1 element per thread)
        {
            const int i = gthr;                  // 0..32767
            const int bb = i >> 9, j = i & 511;
            const int gbase = bb * N3 + j;
            const int rbase = bb * NR + Dn + j;
            float gir = b_ih[j], giz = b_ih[Dn + j], gin_ = b_ih[2 * Dn + j];
            float ghr = b_hh[j], ghz = b_hh[Dn + j], ghn = b_hh[2 * Dn + j];
            #pragma unroll
            for (int p = 0; p < 4; ++p) {
                gir  += g_gipart[p][gbase];
                giz  += g_gipart[p][gbase + Dn];
                gin_ += g_gipart[p][gbase + 2 * Dn];
                ghr  += g_recpart[p][rbase];
                ghz  += g_recpart[p][rbase + Dn];
                ghn  += g_recpart[p][rbase + 2 * Dn];
            }
            float r = 1.f / (1.f + __expf(-(gir + ghr)));
            float z = 1.f / (1.f + __expf(-(giz + ghz)));
            float n = tanhf(gin_ + r * ghn);
            float h = g_h[i];
            g_h[i] = (1.f - z) * n + z * h;
        }
        grid_sync();
    }

    // ---------- final: hT copy + out[T-1] ----------
    for (int j = gthr; j < Bn * Dn; j += NCTA * 256) hT[j] = g_h[j];
    if (cta == 0 && tid < 192) {
        int bb = tid / 3, c = tid - bb * 3;
        const float* hr = &g_h[bb * Dn];
        float acc = Wo_b[c];
        #pragma unroll 4
        for (int k = 0; k < Dn; ++k) acc += hr[k] * Wo_w[k * 3 + c];
        d_outputs[((size_t)bb * Tn + (Tn - 1)) * 3 + c] = acc;
    }
}

// ---------------- launch ----------------
extern "C" void kernel_launch(void* const* d_in, const int* in_sizes, int n_in,
                              void* d_out, int out_size)
{
    const float* e_all  = (const float*)d_in[0];
    const float* e_last = (const float*)d_in[1];
    const float* Wa_w   = (const float*)d_in[2];
    const float* Wa_b   = (const float*)d_in[3];
    const float* Ua_w   = (const float*)d_in[4];
    const float* Ua_b   = (const float*)d_in[5];
    const float* Va_w   = (const float*)d_in[6];
    const float* Va_b   = (const float*)d_in[7];
    const float* W_ih   = (const float*)d_in[8];
    const float* W_hh   = (const float*)d_in[9];
    const float* b_ih   = (const float*)d_in[10];
    const float* b_hh   = (const float*)d_in[11];
    const float* Wo_w   = (const float*)d_in[12];
    const float* Wo_b   = (const float*)d_in[13];

    float* out       = (float*)d_out;
    float* d_outputs = out;                        // [B,T,3]
    float* hT        = out + Bn * Tn * 3;          // [1,B,D]
    float* cross     = hT + Bn * Dn;               // [B,T,S]

    k_persist<<<NCTA, 256>>>(e_all, e_last, Wa_w, Wa_b, Ua_w, Ua_b,
                             Va_w, Va_b, W_ih, W_hh, b_ih, b_hh,
                             Wo_w, Wo_b, d_outputs, hT, cross);
}

// round 5
// speedup vs baseline: 1.9784x; 1.9784x over previous
#include <cuda_runtime.h>
#include <cstdint>

#define Bn 64
#define Sn 128
#define Dn 512
#define Tn 64
#define N3 1536      // 3*D
#define GK 515       // D + 3
#define GKP 528      // padded to multiple of 16

// ---------------- scratch (device globals; no allocation) ----------------
__device__ float g_Uk[Bn * Sn * Dn];        // [B,S,D] keys projection
__device__ float g_h[Bn * Dn];              // hidden state (in-place update)
__device__ float g_qpart[8][Bn * Dn];       // split-K partials of q
__device__ float g_gipart[4][Bn * N3];      // split-K partials of gi
__device__ float g_ghpart[4][Bn * N3];      // split-K partials of gh
__device__ float g_gin[Bn * GKP];           // [ctx | x | zero-pad]
__device__ float g_Wpad[N3 * GKP];          // W_ih zero-padded to K=528
__device__ float g_scores[Bn * Sn];         // attention scores
__device__ unsigned g_arr4[Bn * 8];         // per-batch group-sync (monotonic)
__device__ unsigned g_rel4[Bn * 8];         //   stride 8 -> 32B sector spacing

__device__ __forceinline__ float tanh_fast(float x) {
    float y; asm("tanh.approx.f32 %0, %1;" : "=f"(y) : "f"(x)); return y;
}

__device__ __forceinline__ float gru_one(float gir, float ghr, float giz, float ghz,
                                         float gnn, float ghn, float h) {
    float r = 1.f / (1.f + __expf(-(gir + ghr)));
    float z = 1.f / (1.f + __expf(-(giz + ghz)));
    float n = tanhf(gnn + r * ghn);
    return (1.f - z) * n + z * h;
}

__device__ __forceinline__ void add4(float4& a, const float* p) {
    float4 v = *(const float4*)p;
    a.x += v.x; a.y += v.y; a.z += v.z; a.w += v.w;
}

struct SmemGemm { float As[16][68]; float Bs[16][68]; };

// C[64 x 64] tile of  C = A(MxK) * B  (+bias), BK=16, 256 threads, 4x4 microtile.
// NT=false: B row-major [K,N];  NT=true: B row-major [N,K].
template <bool NT>
__device__ __forceinline__ void gemm64(const float* __restrict__ A, int lda,
                                       const float* __restrict__ B, int ldb,
                                       float* __restrict__ C, int ldc,
                                       const float* __restrict__ bias,
                                       int m0, int n0, int k0, int kiters,
                                       SmemGemm& s)
{
    const int tid = threadIdx.x;
    const int tx = tid & 15, ty = tid >> 4;
    const int am = tid >> 2, ak = (tid & 3) << 2;
    float acc[4][4] = {};

    for (int it = 0; it < kiters; ++it) {
        const int k = k0 + it * 16;
        float4 a4 = *(const float4*)&A[(size_t)(m0 + am) * lda + k + ak];
        float4 b4;
        if (NT) {
            b4 = *(const float4*)&B[(size_t)(n0 + am) * ldb + k + ak];
        } else {
            const int bk = tid >> 4, bn = (tid & 15) << 2;
            b4 = *(const float4*)&B[(size_t)(k + bk) * ldb + n0 + bn];
        }
        __syncthreads();
        s.As[ak + 0][am] = a4.x; s.As[ak + 1][am] = a4.y;
        s.As[ak + 2][am] = a4.z; s.As[ak + 3][am] = a4.w;
        if (NT) {
            s.Bs[ak + 0][am] = b4.x; s.Bs[ak + 1][am] = b4.y;
            s.Bs[ak + 2][am] = b4.z; s.Bs[ak + 3][am] = b4.w;
        } else {
            const int bk = tid >> 4, bn = (tid & 15) << 2;
            *(float4*)&s.Bs[bk][bn] = b4;
        }
        __syncthreads();
        #pragma unroll
        for (int kk = 0; kk < 16; ++kk) {
            float4 av = *(const float4*)&s.As[kk][ty << 2];
            float4 bv = *(const float4*)&s.Bs[kk][tx << 2];
            float a[4] = {av.x, av.y, av.z, av.w};
            float b[4] = {bv.x, bv.y, bv.z, bv.w};
            #pragma unroll
            for (int u = 0; u < 4; ++u)
                #pragma unroll
                for (int v = 0; v < 4; ++v)
                    acc[u][v] += a[u] * b[v];
        }
    }

    float4 bi = make_float4(0.f, 0.f, 0.f, 0.f);
    if (bias) bi = *(const float4*)&bias[n0 + (tx << 2)];
    #pragma unroll
    for (int u = 0; u < 4; ++u) {
        float4 o;
        o.x = acc[u][0] + bi.x; o.y = acc[u][1] + bi.y;
        o.z = acc[u][2] + bi.z; o.w = acc[u][3] + bi.w;
        *(float4*)&C[(size_t)(m0 + (ty << 2) + u) * ldc + n0 + (tx << 2)] = o;
    }
}

// ---------------- kernels ----------------

__global__ void k_init(const float* __restrict__ e_last,
                       const float* __restrict__ W_ih)
{
    const int i = blockIdx.x * blockDim.x + threadIdx.x;
    const int stride = gridDim.x * blockDim.x;
    if (i < Bn * Dn) g_h[i] = e_last[i];
    if (i < Bn * 16) {                     // zero x + pad region of gin
        int b = i >> 4, k = i & 15;
        g_gin[b * GKP + Dn + k] = 0.f;
    }
    for (int j = i; j < N3 * GKP; j += stride) {
        int n = j / GKP, k = j - n * GKP;
        g_Wpad[j] = (k < GK) ? W_ih[n * GK + k] : 0.f;
    }
}

// Uk = e_all @ Ua_w + Ua_b    (M = B*S = 8192, N = K = 512)
__global__ void k_uk(const float* __restrict__ e_all,
                     const float* __restrict__ Ua_w,
                     const float* __restrict__ Ua_b)
{
    __shared__ SmemGemm s;
    gemm64<false>(e_all, Dn, Ua_w, Dn, g_Uk, Dn, Ua_b,
                  blockIdx.y * 64, blockIdx.x * 64, 0, 32, s);
}

// GRU gates: h(in) + parts -> h(out).  4 elems/thread, float4.  grid = 32 CTAs.
__global__ void k_gates(const float* __restrict__ b_ih,
                        const float* __restrict__ b_hh,
                        const float* __restrict__ hin,
                        float* __restrict__ hout)
{
    const int g = (blockIdx.x * 256 + threadIdx.x) << 2;  // 0..32764 step 4
    const int b = g >> 9, j = g & 511;
    const int gb = b * N3 + j;

    float4 gir = *(const float4*)&b_ih[j];
    float4 giz = *(const float4*)&b_ih[Dn + j];
    float4 gnn = *(const float4*)&b_ih[2 * Dn + j];
    float4 ghr = *(const float4*)&b_hh[j];
    float4 ghz = *(const float4*)&b_hh[Dn + j];
    float4 ghn = *(const float4*)&b_hh[2 * Dn + j];
    #pragma unroll
    for (int p = 0; p < 4; ++p) {
        add4(gir, &g_gipart[p][gb]);
        add4(giz, &g_gipart[p][gb + Dn]);
        add4(gnn, &g_gipart[p][gb + 2 * Dn]);
        add4(ghr, &g_ghpart[p][gb]);
        add4(ghz, &g_ghpart[p][gb + Dn]);
        add4(ghn, &g_ghpart[p][gb + 2 * Dn]);
    }
    float4 h4 = *(const float4*)&hin[g];
    float4 o;
    o.x = gru_one(gir.x, ghr.x, giz.x, ghz.x, gnn.x, ghn.x, h4.x);
    o.y = gru_one(gir.y, ghr.y, giz.y, ghz.y, gnn.y, ghn.y, h4.y);
    o.z = gru_one(gir.z, ghr.z, giz.z, ghz.z, gnn.z, ghn.z, h4.z);
    o.w = gru_one(gir.w, ghr.w, giz.w, ghz.w, gnn.w, ghn.w, h4.w);
    *(float4*)&hout[g] = o;
}

// q partials = h @ Wa  (N=512, split-K 8).  grid = 64 CTAs (8 nt x 8 parts).
__global__ void k_q(const float* __restrict__ Wa_w)
{
    __shared__ SmemGemm s;
    const int part = blockIdx.x & 7, nt = blockIdx.x >> 3;
    gemm64<false>(g_h, Dn, Wa_w, Dn, g_qpart[part], Dn, nullptr,
                  0, nt * 64, part * 64, 4, s);
}

// fused attention: scores (32 rows/CTA) -> 4-CTA group sync -> softmax -> ctx.
// grid = B*4 CTAs, 256 threads.  quad 3 also computes out_{t-1}.
__global__ void k_attn(const float* __restrict__ e_all,
                       const float* __restrict__ Wa_b,
                       const float* __restrict__ Va_w,
                       const float* __restrict__ Va_b,
                       const float* __restrict__ Wo_w,
                       const float* __restrict__ Wo_b,
                       float* __restrict__ d_outputs,
                       float* __restrict__ cross, int t)
{
    __shared__ float qs[Dn];
    __shared__ float vas[Dn];
    __shared__ float ws[Sn];
    __shared__ float cs[2][128];
    __shared__ float red[8];
    __shared__ float smax, sinv;

    const int tid = threadIdx.x;
    const int lane = tid & 31, wid = tid >> 5;
    const int b = blockIdx.x >> 2, quad = blockIdx.x & 3;

    // q = sum of 8 parts + bias
    for (int d = tid; d < Dn; d += 256) {
        float q = Wa_b[d];
        #pragma unroll
        for (int p = 0; p < 8; ++p) q += g_qpart[p][b * Dn + d];
        qs[d] = q;
        vas[d] = Va_w[d];
    }
    __syncthreads();

    // scores: 32 rows per CTA (4 per warp)
    const float vb0 = Va_b[0];
    #pragma unroll
    for (int r = 0; r < 4; ++r) {
        const int s = quad * 32 + wid * 4 + r;
        const float4* uk4 = (const float4*)(g_Uk + ((size_t)b * Sn + s) * Dn);
        float sum = 0.f;
        #pragma unroll
        for (int i = 0; i < 4; ++i) {
            const int v = lane + (i << 5);
            float4 u = uk4[v];
            float4 q4 = *(const float4*)&qs[v << 2];
            float4 a4 = *(const float4*)&vas[v << 2];
            sum += tanh_fast(q4.x + u.x) * a4.x;
            sum += tanh_fast(q4.y + u.y) * a4.y;
            sum += tanh_fast(q4.z + u.z) * a4.z;
            sum += tanh_fast(q4.w + u.w) * a4.w;
        }
        #pragma unroll
        for (int o = 16; o > 0; o >>= 1)
            sum += __shfl_down_sync(0xffffffffu, sum, o);
        if (lane == 0) g_scores[b * Sn + s] = sum + vb0;
    }

    // out_{t-1} = h_t @ Wo  (quad 3, 3 warps; h already updated this step)
    if (quad == 3 && t > 0 && tid < 96) {
        const int c = tid >> 5;
        const float* hr = &g_h[b * Dn];
        float acc = 0.f;
        for (int k = lane; k < Dn; k += 32) acc += hr[k] * Wo_w[k * 3 + c];
        #pragma unroll
        for (int o = 16; o > 0; o >>= 1)
            acc += __shfl_down_sync(0xffffffffu, acc, o);
        if (lane == 0) {
            acc += Wo_b[c];
            d_outputs[((size_t)b * Tn + (t - 1)) * 3 + c] = acc;
            g_gin[b * GKP + Dn + c] = acc;
        }
    }

    // replay-safe monotonic 4-CTA group sync
    __syncthreads();
    if (tid == 0) {
        __threadfence();
        unsigned old;
        asm volatile("atom.acq_rel.gpu.add.u32 %0, [%1], 1;"
                     : "=r"(old) : "l"(&g_arr4[b * 8]) : "memory");
        const unsigned k = old >> 2;
        if ((old & 3u) == 3u) {
            asm volatile("st.release.gpu.u32 [%0], %1;"
                         :: "l"(&g_rel4[b * 8]), "r"(k + 1) : "memory");
        } else {
            unsigned r;
            do {
                asm volatile("ld.acquire.gpu.u32 %0, [%1];"
                             : "=r"(r) : "l"(&g_rel4[b * 8]) : "memory");
            } while (r < k + 1);
        }
    }
    __syncthreads();

    // softmax over S=128 (redundant per CTA)
    float sc = (tid < Sn) ? __ldcg(&g_scores[b * Sn + tid]) : -3.4e38f;
    float v = sc;
    #pragma unroll
    for (int o = 16; o > 0; o >>= 1)
        v = fmaxf(v, __shfl_xor_sync(0xffffffffu, v, o));
    if (lane == 0) red[wid] = v;
    __syncthreads();
    if (tid == 0) {
        float m = red[0];
        #pragma unroll
        for (int i = 1; i < 8; ++i) m = fmaxf(m, red[i]);
        smax = m;
    }
    __syncthreads();
    float e = (tid < Sn) ? __expf(sc - smax) : 0.f;
    float es = e;
    #pragma unroll
    for (int o = 16; o > 0; o >>= 1)
        es += __shfl_xor_sync(0xffffffffu, es, o);
    if (lane == 0) red[wid] = es;
    __syncthreads();
    if (tid == 0) {
        float s2 = 0.f;
        #pragma unroll
        for (int i = 0; i < 8; ++i) s2 += red[i];
        sinv = 1.f / s2;
    }
    __syncthreads();
    if (tid < Sn) {
        float w = e * sinv;
        ws[tid] = w;
        if (quad == 0) cross[((size_t)b * Tn + t) * Sn + tid] = w;
    }
    __syncthreads();

    // ctx: 128 cols per CTA, s-dim split in half across thread halves
    const int dl = tid & 127, sh = tid >> 7;
    const int d = quad * 128 + dl;
    const float* eb = e_all + (size_t)b * Sn * Dn + d;
    float a = 0.f;
    #pragma unroll 8
    for (int s = sh * 64; s < sh * 64 + 64; ++s)
        a += ws[s] * eb[(size_t)s * Dn];
    cs[sh][dl] = a;
    __syncthreads();
    if (tid < 128)
        g_gin[b * GKP + quad * 128 + tid] = cs[0][tid] + cs[1][tid];
}

// gi partials (96 CTAs) + gh partials (96 CTAs) in one launch
__global__ void k_gigh(const float* __restrict__ W_hh)
{
    __shared__ SmemGemm s;
    const int bx = blockIdx.x;
    if (bx < 96) {
        const int part = bx & 3, nt = bx >> 2;
        const int k0 = (part < 3) ? part * 128 : 384;
        const int ki = (part < 3) ? 8 : 9;
        gemm64<true>(g_gin, GKP, g_Wpad, GKP, g_gipart[part], N3, nullptr,
                     0, nt * 64, k0, ki, s);
    } else {
        const int i = bx - 96;
        const int part = i & 3, nt = i >> 2;
        gemm64<true>(g_h, Dn, W_hh, Dn, g_ghpart[part], N3, nullptr,
                     0, nt * 64, part * 128, 8, s);
    }
}

// final out row: d_outputs[:, T-1] = hT @ Wo + b
__global__ void k_fout(const float* __restrict__ hT,
                       const float* __restrict__ Wo_w,
                       const float* __restrict__ Wo_b,
                       float* __restrict__ d_outputs)
{
    const int b = blockIdx.x;
    const int c = threadIdx.x >> 5, lane = threadIdx.x & 31;
    const float* hr = hT + (size_t)b * Dn;
    float acc = 0.f;
    for (int k = lane; k < Dn; k += 32) acc += hr[k] * Wo_w[k * 3 + c];
    #pragma unroll
    for (int o = 16; o > 0; o >>= 1)
        acc += __shfl_down_sync(0xffffffffu, acc, o);
    if (lane == 0)
        d_outputs[((size_t)b * Tn + (Tn - 1)) * 3 + c] = acc + Wo_b[c];
}

// ---------------- launch ----------------
extern "C" void kernel_launch(void* const* d_in, const int* in_sizes, int n_in,
                              void* d_out, int out_size)
{
    const float* e_all  = (const float*)d_in[0];
    const float* e_last = (const float*)d_in[1];
    const float* Wa_w   = (const float*)d_in[2];
    const float* Wa_b   = (const float*)d_in[3];
    const float* Ua_w   = (const float*)d_in[4];
    const float* Ua_b   = (const float*)d_in[5];
    const float* Va_w   = (const float*)d_in[6];
    const float* Va_b   = (const float*)d_in[7];
    const float* W_ih   = (const float*)d_in[8];
    const float* W_hh   = (const float*)d_in[9];
    const float* b_ih   = (const float*)d_in[10];
    const float* b_hh   = (const float*)d_in[11];
    const float* Wo_w   = (const float*)d_in[12];
    const float* Wo_b   = (const float*)d_in[13];

    float* out       = (float*)d_out;
    float* d_outputs = out;                        // [B,T,3]
    float* hT        = out + Bn * Tn * 3;          // [1,B,D]
    float* cross     = hT + Bn * Dn;               // [B,T,S]

    float* g_h_ptr = nullptr;
    cudaGetSymbolAddress((void**)&g_h_ptr, g_h);

    k_init<<<512, 256>>>(e_last, W_ih);
    k_uk<<<dim3(Dn / 64, (Bn * Sn) / 64), 256>>>(e_all, Ua_w, Ua_b);

    for (int t = 0; t < Tn; ++t) {
        if (t > 0)
            k_gates<<<32, 256>>>(b_ih, b_hh, g_h_ptr, g_h_ptr);   // h <- GRU(h, parts)
        k_q<<<64, 256>>>(Wa_w);
        k_attn<<<Bn * 4, 256>>>(e_all, Wa_b, Va_w, Va_b, Wo_w, Wo_b,
                                d_outputs, cross, t);
        k_gigh<<<192, 256>>>(W_hh);
    }
    k_gates<<<32, 256>>>(b_ih, b_hh, g_h_ptr, hT);                // hT = final h
    k_fout<<<Bn, 96>>>(hT, Wo_w, Wo_b, d_outputs);
}

// round 7
// speedup vs baseline: 2.3683x; 1.1971x over previous
#include <cuda_runtime.h>
#include <cstdint>

#define Bn 64
#define Sn 128
#define Dn 512
#define Tn 64
#define N3 1536      // 3*D
#define GK 515       // D + 3
#define GKP 528      // padded to multiple of 16

// ---------------- scratch (device globals; no allocation) ----------------
__device__ float g_Uk[Bn * Sn * Dn];        // [B,S,D] keys projection
__device__ float g_h[Bn * Dn];              // hidden state (in-place update)
__device__ float g_qpart[8][Bn * Dn];       // split-K partials of q
__device__ float g_gipart[4][Bn * N3];      // split-K partials of gi
__device__ float g_ghpart[4][Bn * N3];      // split-K partials of gh
__device__ float g_gin[Bn * GKP];           // [ctx | x | zero-pad]
__device__ float g_Wpad[N3 * GKP];          // W_ih zero-padded to K=528

__device__ __forceinline__ float tanh_fast(float x) {
    float y; asm("tanh.approx.f32 %0, %1;" : "=f"(y) : "f"(x)); return y;
}

__device__ __forceinline__ float gru_one(float gir, float ghr, float giz, float ghz,
                                         float gnn, float ghn, float h) {
    float r = 1.f / (1.f + __expf(-(gir + ghr)));
    float z = 1.f / (1.f + __expf(-(giz + ghz)));
    float n = tanhf(gnn + r * ghn);
    return (1.f - z) * n + z * h;
}

__device__ __forceinline__ void add4(float4& a, const float* p) {
    float4 v = *(const float4*)p;
    a.x += v.x; a.y += v.y; a.z += v.z; a.w += v.w;
}

struct SmemGemm { float As[16][68]; float Bs[16][68]; };

// C[64 x 64] tile of  C = A(MxK) * B  (+bias), BK=16, 256 threads, 4x4 microtile.
// NT=false: B row-major [K,N];  NT=true: B row-major [N,K].
template <bool NT>
__device__ __forceinline__ void gemm64(const float* __restrict__ A, int lda,
                                       const float* __restrict__ B, int ldb,
                                       float* __restrict__ C, int ldc,
                                       const float* __restrict__ bias,
                                       int m0, int n0, int k0, int kiters,
                                       SmemGemm& s)
{
    const int tid = threadIdx.x;
    const int tx = tid & 15, ty = tid >> 4;
    const int am = tid >> 2, ak = (tid & 3) << 2;
    float acc[4][4] = {};

    for (int it = 0; it < kiters; ++it) {
        const int k = k0 + it * 16;
        float4 a4 = *(const float4*)&A[(size_t)(m0 + am) * lda + k + ak];
        float4 b4;
        if (NT) {
            b4 = *(const float4*)&B[(size_t)(n0 + am) * ldb + k + ak];
        } else {
            const int bk = tid >> 4, bn = (tid & 15) << 2;
            b4 = *(const float4*)&B[(size_t)(k + bk) * ldb + n0 + bn];
        }
        __syncthreads();
        s.As[ak + 0][am] = a4.x; s.As[ak + 1][am] = a4.y;
        s.As[ak + 2][am] = a4.z; s.As[ak + 3][am] = a4.w;
        if (NT) {
            s.Bs[ak + 0][am] = b4.x; s.Bs[ak + 1][am] = b4.y;
            s.Bs[ak + 2][am] = b4.z; s.Bs[ak + 3][am] = b4.w;
        } else {
            const int bk = tid >> 4, bn = (tid & 15) << 2;
            *(float4*)&s.Bs[bk][bn] = b4;
        }
        __syncthreads();
        #pragma unroll
        for (int kk = 0; kk < 16; ++kk) {
            float4 av = *(const float4*)&s.As[kk][ty << 2];
            float4 bv = *(const float4*)&s.Bs[kk][tx << 2];
            float a[4] = {av.x, av.y, av.z, av.w};
            float b[4] = {bv.x, bv.y, bv.z, bv.w};
            #pragma unroll
            for (int u = 0; u < 4; ++u)
                #pragma unroll
                for (int v = 0; v < 4; ++v)
                    acc[u][v] += a[u] * b[v];
        }
    }

    float4 bi = make_float4(0.f, 0.f, 0.f, 0.f);
    if (bias) bi = *(const float4*)&bias[n0 + (tx << 2)];
    #pragma unroll
    for (int u = 0; u < 4; ++u) {
        float4 o;
        o.x = acc[u][0] + bi.x; o.y = acc[u][1] + bi.y;
        o.z = acc[u][2] + bi.z; o.w = acc[u][3] + bi.w;
        *(float4*)&C[(size_t)(m0 + (ty << 2) + u) * ldc + n0 + (tx << 2)] = o;
    }
}

// ---------------- kernels ----------------

__global__ void k_init(const float* __restrict__ e_last,
                       const float* __restrict__ W_ih)
{
    const int i = blockIdx.x * blockDim.x + threadIdx.x;
    const int stride = gridDim.x * blockDim.x;
    if (i < Bn * Dn) g_h[i] = e_last[i];
    if (i < Bn * 16) {                     // zero x + pad region of gin
        int b = i >> 4, k = i & 15;
        g_gin[b * GKP + Dn + k] = 0.f;
    }
    for (int j = i; j < N3 * GKP; j += stride) {
        int n = j / GKP, k = j - n * GKP;
        g_Wpad[j] = (k < GK) ? W_ih[n * GK + k] : 0.f;
    }
}

// Uk = e_all @ Ua_w + Ua_b    (M = B*S = 8192, N = K = 512)
__global__ void k_uk(const float* __restrict__ e_all,
                     const float* __restrict__ Ua_w,
                     const float* __restrict__ Ua_b)
{
    __shared__ SmemGemm s;
    gemm64<false>(e_all, Dn, Ua_w, Dn, g_Uk, Dn, Ua_b,
                  blockIdx.y * 64, blockIdx.x * 64, 0, 32, s);
}

// GRU gates: h(in)+parts -> h(out), PLUS out = h_new @ Wo + b (written to
// d_outputs[:, tout] and g_gin x-slot).  grid = 32 CTAs x 256 thr; CTA owns
// exactly 2 full batch rows.
__global__ void k_gates(const float* __restrict__ b_ih,
                        const float* __restrict__ b_hh,
                        const float* __restrict__ hin,
                        float* __restrict__ hout,
                        const float* __restrict__ Wo_w,
                        const float* __restrict__ Wo_b,
                        float* __restrict__ d_outputs,
                        int tout)
{
    __shared__ float so[8][3];
    const int tid = threadIdx.x;
    const int lane = tid & 31, wid = tid >> 5;
    const int g = (blockIdx.x * 256 + tid) << 2;  // element base (step 4)
    const int b = g >> 9, j = g & 511;
    const int gb = b * N3 + j;

    // biases: scalar loads (input alignment not guaranteed for vectors)
    float4 gir = make_float4(b_ih[j], b_ih[j + 1], b_ih[j + 2], b_ih[j + 3]);
    float4 giz = make_float4(b_ih[Dn + j], b_ih[Dn + j + 1],
                             b_ih[Dn + j + 2], b_ih[Dn + j + 3]);
    float4 gnn = make_float4(b_ih[2 * Dn + j], b_ih[2 * Dn + j + 1],
                             b_ih[2 * Dn + j + 2], b_ih[2 * Dn + j + 3]);
    float4 ghr = make_float4(b_hh[j], b_hh[j + 1], b_hh[j + 2], b_hh[j + 3]);
    float4 ghz = make_float4(b_hh[Dn + j], b_hh[Dn + j + 1],
                             b_hh[Dn + j + 2], b_hh[Dn + j + 3]);
    float4 ghn = make_float4(b_hh[2 * Dn + j], b_hh[2 * Dn + j + 1],
                             b_hh[2 * Dn + j + 2], b_hh[2 * Dn + j + 3]);
    #pragma unroll
    for (int p = 0; p < 4; ++p) {
        add4(gir, &g_gipart[p][gb]);
        add4(giz, &g_gipart[p][gb + Dn]);
        add4(gnn, &g_gipart[p][gb + 2 * Dn]);
        add4(ghr, &g_ghpart[p][gb]);
        add4(ghz, &g_ghpart[p][gb + Dn]);
        add4(ghn, &g_ghpart[p][gb + 2 * Dn]);
    }
    float4 h4 = *(const float4*)&hin[g];
    float4 o;
    o.x = gru_one(gir.x, ghr.x, giz.x, ghz.x, gnn.x, ghn.x, h4.x);
    o.y = gru_one(gir.y, ghr.y, giz.y, ghz.y, gnn.y, ghn.y, h4.y);
    o.z = gru_one(gir.z, ghr.z, giz.z, ghz.z, gnn.z, ghn.z, h4.z);
    o.w = gru_one(gir.w, ghr.w, giz.w, ghz.w, gnn.w, ghn.w, h4.w);
    *(float4*)&hout[g] = o;

    // out[b, c] = sum_j h_new[b,j] * Wo[j,c]  (scalar Wo loads; L1-resident)
    const float* wp = &Wo_w[j * 3];
    float p0 = o.x * wp[0] + o.y * wp[3] + o.z * wp[6] + o.w * wp[9];
    float p1 = o.x * wp[1] + o.y * wp[4] + o.z * wp[7] + o.w * wp[10];
    float p2 = o.x * wp[2] + o.y * wp[5] + o.z * wp[8] + o.w * wp[11];
    #pragma unroll
    for (int off = 16; off > 0; off >>= 1) {
        p0 += __shfl_down_sync(0xffffffffu, p0, off);
        p1 += __shfl_down_sync(0xffffffffu, p1, off);
        p2 += __shfl_down_sync(0xffffffffu, p2, off);
    }
    if (lane == 0) { so[wid][0] = p0; so[wid][1] = p1; so[wid][2] = p2; }
    __syncthreads();
    if ((tid & 127) < 3) {                 // tid 0..2 -> warps 0-3 (batch 2*cta),
        const int c = tid & 127;           // tid 128..130 -> warps 4-7 (batch +1)
        const int w0i = (tid >> 7) << 2;
        const int bb = blockIdx.x * 2 + (tid >> 7);
        float acc = so[w0i][c] + so[w0i + 1][c] + so[w0i + 2][c] + so[w0i + 3][c]
                  + Wo_b[c];
        d_outputs[((size_t)bb * Tn + tout) * 3 + c] = acc;
        g_gin[bb * GKP + Dn + c] = acc;
    }
}

// q partials = h @ Wa  (N=512, split-K 8).  grid = 64 CTAs (8 nt x 8 parts).
__global__ void k_q(const float* __restrict__ Wa_w)
{
    __shared__ SmemGemm s;
    const int part = blockIdx.x & 7, nt = blockIdx.x >> 3;
    gemm64<false>(g_h, Dn, Wa_w, Dn, g_qpart[part], Dn, nullptr,
                  0, nt * 64, part * 64, 4, s);
}

// fused per-batch attention: one 1024-thread CTA per batch. scores -> softmax
// -> ctx, all CTA-local (__syncthreads only).  grid = 64.
__global__ void __launch_bounds__(1024, 1)
k_attn(const float* __restrict__ e_all,
       const float* __restrict__ Wa_b,
       const float* __restrict__ Va_w,
       const float* __restrict__ Va_b,
       float* __restrict__ cross, int t)
{
    __shared__ __align__(16) float cpart[8][Dn];   // 16KB, float4-accessed
    __shared__ __align__(16) float qs[Dn];
    __shared__ __align__(16) float vas[Dn];
    __shared__ __align__(16) float ws[Sn];
    __shared__ float red[4];
    __shared__ float smax, sinv;

    const int tid = threadIdx.x;
    const int lane = tid & 31, wid = tid >> 5;
    const int b = blockIdx.x;

    // q = sum of 8 parts + bias (512 threads), Va -> smem
    if (tid < Dn) {
        float q = Wa_b[tid];
        #pragma unroll
        for (int p = 0; p < 8; ++p) q += g_qpart[p][b * Dn + tid];
        qs[tid] = q;
        vas[tid] = Va_w[tid];
    }
    __syncthreads();

    // scores: 32 warps x 4 rows
    const float vb0 = Va_b[0];
    #pragma unroll
    for (int r = 0; r < 4; ++r) {
        const int s = (wid << 2) + r;
        const float4* uk4 = (const float4*)(g_Uk + ((size_t)b * Sn + s) * Dn);
        float sum = 0.f;
        #pragma unroll
        for (int i = 0; i < 4; ++i) {
            const int v = lane + (i << 5);
            float4 u = uk4[v];
            float4 q4 = *(const float4*)&qs[v << 2];
            float4 a4 = *(const float4*)&vas[v << 2];
            sum += tanh_fast(q4.x + u.x) * a4.x;
            sum += tanh_fast(q4.y + u.y) * a4.y;
            sum += tanh_fast(q4.z + u.z) * a4.z;
            sum += tanh_fast(q4.w + u.w) * a4.w;
        }
        #pragma unroll
        for (int o = 16; o > 0; o >>= 1)
            sum += __shfl_down_sync(0xffffffffu, sum, o);
        if (lane == 0) ws[s] = sum + vb0;
    }
    __syncthreads();

    // softmax over S=128 (first 4 warps)
    float sc = (tid < Sn) ? ws[tid] : -3.4e38f;
    if (tid < Sn) {
        float v = sc;
        #pragma unroll
        for (int o = 16; o > 0; o >>= 1)
            v = fmaxf(v, __shfl_xor_sync(0xffffffffu, v, o));
        if (lane == 0) red[wid] = v;
    }
    __syncthreads();
    if (tid == 0)
        smax = fmaxf(fmaxf(red[0], red[1]), fmaxf(red[2], red[3]));
    __syncthreads();
    float e = 0.f;
    if (tid < Sn) {
        e = __expf(sc - smax);
        float es = e;
        #pragma unroll
        for (int o = 16; o > 0; o >>= 1)
            es += __shfl_xor_sync(0xffffffffu, es, o);
        if (lane == 0) red[wid] = es;
    }
    __syncthreads();
    if (tid == 0)
        sinv = 1.f / (red[0] + red[1] + red[2] + red[3]);
    __syncthreads();
    if (tid < Sn) {
        float w = e * sinv;
        ws[tid] = w;
        cross[((size_t)b * Tn + t) * Sn + tid] = w;
    }
    __syncthreads();

    // ctx: thread handles float4 of d (128 groups), 8 s-groups of 16
    {
        const int d4 = (tid & 127) << 2;
        const int sg = tid >> 7;
        const float4* eb = (const float4*)(e_all + (size_t)b * Sn * Dn + d4);
        float4 a = make_float4(0.f, 0.f, 0.f, 0.f);
        #pragma unroll
        for (int s = sg << 4; s < (sg << 4) + 16; ++s) {
            float4 v = eb[(size_t)s * (Dn / 4)];
            float w = ws[s];
            a.x += w * v.x; a.y += w * v.y; a.z += w * v.z; a.w += w * v.w;
        }
        *(float4*)&cpart[sg][d4] = a;
    }
    __syncthreads();
    if (tid < Dn) {
        float a = 0.f;
        #pragma unroll
        for (int sg = 0; sg < 8; ++sg) a += cpart[sg][tid];
        g_gin[b * GKP + tid] = a;
    }
}

// gi partials (96 CTAs) + gh partials (96 CTAs) in one launch
__global__ void k_gigh(const float* __restrict__ W_hh)
{
    __shared__ SmemGemm s;
    const int bx = blockIdx.x;
    if (bx < 96) {
        const int part = bx & 3, nt = bx >> 2;
        const int k0 = (part < 3) ? part * 128 : 384;
        const int ki = (part < 3) ? 8 : 9;
        gemm64<true>(g_gin, GKP, g_Wpad, GKP, g_gipart[part], N3, nullptr,
                     0, nt * 64, k0, ki, s);
    } else {
        const int i = bx - 96;
        const int part = i & 3, nt = i >> 2;
        gemm64<true>(g_h, Dn, W_hh, Dn, g_ghpart[part], N3, nullptr,
                     0, nt * 64, part * 128, 8, s);
    }
}

// ---------------- launch ----------------
extern "C" void kernel_launch(void* const* d_in, const int* in_sizes, int n_in,
                              void* d_out, int out_size)
{
    const float* e_all  = (const float*)d_in[0];
    const float* e_last = (const float*)d_in[1];
    const float* Wa_w   = (const float*)d_in[2];
    const float* Wa_b   = (const float*)d_in[3];
    const float* Ua_w   = (const float*)d_in[4];
    const float* Ua_b   = (const float*)d_in[5];
    const float* Va_w   = (const float*)d_in[6];
    const float* Va_b   = (const float*)d_in[7];
    const float* W_ih   = (const float*)d_in[8];
    const float* W_hh   = (const float*)d_in[9];
    const float* b_ih   = (const float*)d_in[10];
    const float* b_hh   = (const float*)d_in[11];
    const float* Wo_w   = (const float*)d_in[12];
    const float* Wo_b   = (const float*)d_in[13];

    float* out       = (float*)d_out;
    float* d_outputs = out;                        // [B,T,3]
    float* hT        = out + Bn * Tn * 3;          // [1,B,D]
    float* cross     = hT + Bn * Dn;               // [B,T,S]

    float* g_h_ptr = nullptr;
    cudaGetSymbolAddress((void**)&g_h_ptr, g_h);

    k_init<<<512, 256>>>(e_last, W_ih);
    k_uk<<<dim3(Dn / 64, (Bn * Sn) / 64), 256>>>(e_all, Ua_w, Ua_b);

    for (int t = 0; t < Tn; ++t) {
        if (t > 0)
            k_gates<<<32, 256>>>(b_ih, b_hh, g_h_ptr, g_h_ptr,
                                 Wo_w, Wo_b, d_outputs, t - 1);
        k_q<<<64, 256>>>(Wa_w);
        k_attn<<<Bn, 1024>>>(e_all, Wa_b, Va_w, Va_b, cross, t);
        k_gigh<<<192, 256>>>(W_hh);
    }
    k_gates<<<32, 256>>>(b_ih, b_hh, g_h_ptr, hT,
                         Wo_w, Wo_b, d_outputs, Tn - 1);
}